// round 1
// baseline (speedup 1.0000x reference)
#include <cuda_runtime.h>

#define NB 4
#define NA 100000
#define NM 32
#define NC 80

// accumulators: [0]=cls_sum, [1]=reg_sum, [2]=num_pos
__device__ double g_acc[3];
// per-anchor meta: bits 0..6 best class, bit7 pos, bit8 valid
__device__ int g_meta[NB * NA];

__device__ __forceinline__ float warp_sum(float v) {
    #pragma unroll
    for (int o = 16; o > 0; o >>= 1) v += __shfl_down_sync(0xffffffffu, v, o);
    return v;
}

__global__ void zero_kernel() {
    g_acc[0] = 0.0; g_acc[1] = 0.0; g_acc[2] = 0.0;
}

__device__ __forceinline__ float huber(float x) {
    float d = fabsf(x);
    return (d < (1.0f / 9.0f)) ? 4.5f * d * d : d - (0.5f / 9.0f);
}

__global__ void targets_kernel(const float4* __restrict__ anchors,
                               const float4* __restrict__ regression,
                               const float* __restrict__ annotations) {
    __shared__ float sb[NM * 5];
    __shared__ float sred[16];
    const int b = blockIdx.y;
    const int a = blockIdx.x * blockDim.x + threadIdx.x;

    for (int i = threadIdx.x; i < NM * 5; i += blockDim.x)
        sb[i] = annotations[b * NM * 5 + i];
    __syncthreads();

    float reg_c = 0.0f, pos_f = 0.0f;
    if (a < NA) {
        float4 an = anchors[a];
        float area_a = (an.z - an.x) * (an.w - an.y);
        float best_iou = -1.0f;
        int best = 0;
        #pragma unroll
        for (int m = 0; m < NM; m++) {
            float x1 = sb[m * 5 + 0], y1 = sb[m * 5 + 1];
            float x2 = sb[m * 5 + 2], y2 = sb[m * 5 + 3];
            float iw = fminf(an.z, x2) - fmaxf(an.x, x1);
            float ih = fminf(an.w, y2) - fmaxf(an.y, y1);
            float inter = fmaxf(iw, 0.0f) * fmaxf(ih, 0.0f);
            float uni = area_a + (x2 - x1) * (y2 - y1) - inter;
            float iou = inter / fmaxf(uni, 1e-8f);
            if (iou > best_iou) { best_iou = iou; best = m; }
        }
        bool pos = best_iou >= 0.5f;
        bool ign = (best_iou > 0.4f) && !pos;
        float cx = (an.x + an.z) * 0.5f;
        float cy = (an.y + an.w) * 0.5f;
        bool inside = (cx >= 0.0f) && (cx < 800.0f) && (cy >= 0.0f) && (cy < 800.0f);
        int state = inside ? (pos ? 1 : (ign ? -1 : 0)) : -1;
        bool valid = (state != -1);
        int bcls = (int)sb[best * 5 + 4];
        g_meta[b * NA + a] = (pos ? (bcls | 0x80) : 0) | (valid ? 0x100 : 0);

        if (state == 1) {
            pos_f = 1.0f;
            float aw = an.z - an.x, ah = an.w - an.y;
            float bx1 = sb[best * 5 + 0], by1 = sb[best * 5 + 1];
            float bx2 = sb[best * 5 + 2], by2 = sb[best * 5 + 3];
            float t0 = ((bx1 - an.x) / aw) * 5.0f;
            float t1 = ((by1 - an.y) / ah) * 5.0f;
            float t2 = ((bx2 - an.z) / aw) * 5.0f;
            float t3 = ((by2 - an.w) / ah) * 5.0f;
            float4 r = regression[b * NA + a];
            reg_c = huber(r.x - t0) + huber(r.y - t1) + huber(r.z - t2) + huber(r.w - t3);
        }
    }

    // block reduce (256 threads = 8 warps)
    float wr = warp_sum(reg_c);
    float wp = warp_sum(pos_f);
    int wid = threadIdx.x >> 5, lane = threadIdx.x & 31;
    if (lane == 0) { sred[wid] = wr; sred[8 + wid] = wp; }
    __syncthreads();
    if (wid == 0) {
        float vr = (lane < 8) ? sred[lane] : 0.0f;
        float vp = (lane < 8) ? sred[8 + lane] : 0.0f;
        vr = warp_sum(vr);
        vp = warp_sum(vp);
        if (lane == 0) {
            if (vr != 0.0f) atomicAdd(&g_acc[1], (double)vr);
            if (vp != 0.0f) atomicAdd(&g_acc[2], (double)vp);
        }
    }
}

__global__ void focal_kernel(const float4* __restrict__ cls) {
    const int N4 = NB * NA * NC / 4;  // 8,000,000 float4s
    __shared__ float sred[8];
    float acc = 0.0f;
    const int stride = gridDim.x * blockDim.x;
    for (int i = blockIdx.x * blockDim.x + threadIdx.x; i < N4; i += stride) {
        int anchor = i / 20;              // (i*4)/80
        int cbase = (i - anchor * 20) * 4;
        int meta = g_meta[anchor];
        if (!(meta & 0x100)) continue;    // invalid anchor: zero contribution
        int lc = (meta & 0x80) ? (meta & 0x7F) : -2;
        float4 v = cls[i];
        float pv[4] = {v.x, v.y, v.z, v.w};
        #pragma unroll
        for (int j = 0; j < 4; j++) {
            float p = fminf(fmaxf(pv[j], 1e-4f), 1.0f - 1e-4f);
            bool is1 = (cbase + j) == lc;
            float x  = is1 ? p : (1.0f - p);      // log argument
            float w  = is1 ? 0.25f : 0.75f;       // alpha factor
            float om = 1.0f - x;                  // focal base
            acc += w * om * om * (-__logf(x));
        }
    }
    float ws = warp_sum(acc);
    int wid = threadIdx.x >> 5, lane = threadIdx.x & 31;
    if (lane == 0) sred[wid] = ws;
    __syncthreads();
    if (wid == 0) {
        float v = (lane < 8) ? sred[lane] : 0.0f;
        v = warp_sum(v);
        if (lane == 0) atomicAdd(&g_acc[0], (double)v);
    }
}

__global__ void finalize_kernel(float* __restrict__ out) {
    double np = g_acc[2];
    if (np < 1.0) np = 1.0;
    out[0] = (float)((g_acc[0] + g_acc[1]) / np);
}

extern "C" void kernel_launch(void* const* d_in, const int* in_sizes, int n_in,
                              void* d_out, int out_size) {
    const float* cls = (const float*)d_in[0];  // (B, A, 80)
    const float* reg = (const float*)d_in[1];  // (B, A, 4)
    const float* anc = (const float*)d_in[2];  // (A, 4)
    const float* ann = (const float*)d_in[3];  // (B, M, 5)

    zero_kernel<<<1, 1>>>();

    dim3 grid_t((NA + 255) / 256, NB);
    targets_kernel<<<grid_t, 256>>>((const float4*)anc, (const float4*)reg, ann);

    focal_kernel<<<1184, 256>>>((const float4*)cls);

    finalize_kernel<<<1, 1>>>((float*)d_out);
}